// round 3
// baseline (speedup 1.0000x reference)
#include <cuda_runtime.h>

#define B_ 8
#define N_ 2048
#define H_ 128

// Scratch (device globals: allocation-free, graph-safe)
__device__ float g_lin[B_ * N_ * H_];   // h after linear (pre-aggregation)
__device__ float g_nh [B_ * N_ * H_];   // L2-normalized h
__device__ float g_buf[B_ * N_ * H_];   // aggregation output / next-layer input

// ---------------------------------------------------------------------------
// Kernel 1: h = in @ W + b ; nh = h / max(||h||, 1e-12)
// Block: 256 threads, 32 rows. Grid: (N/32, B).
// ---------------------------------------------------------------------------
__global__ __launch_bounds__(256) void lin_norm_kernel(
    const float* __restrict__ in, const float* __restrict__ W,
    const float* __restrict__ bias, float* __restrict__ out_h,
    float* __restrict__ out_nh)
{
    __shared__ float sXT[128 * 33];   // X tile transposed [k][r], stride 33 (conflict-free)
    __shared__ float sW[32 * 132];    // W chunk [kk][c], stride 132
    __shared__ float sPart[32 * 8];
    __shared__ float sRn[32];

    const int tid  = threadIdx.x;
    const int b    = blockIdx.y;
    const int row0 = blockIdx.x * 32;
    const float* X = in + ((size_t)b * N_ + row0) * H_;

    for (int i = tid; i < 32 * 128; i += 256) {
        int r = i >> 7, c = i & 127;
        sXT[c * 33 + r] = X[r * 128 + c];
    }
    __syncthreads();

    const int cx = tid & 15;   // column lane: cols cx + 16*j (conflict-free smem reads)
    const int ry = tid >> 4;   // row group: rows ry*2, ry*2+1
    const int r0 = ry * 2;

    float acc0[8], acc1[8];
#pragma unroll
    for (int j = 0; j < 8; j++) { acc0[j] = 0.f; acc1[j] = 0.f; }

    for (int kt = 0; kt < 128; kt += 32) {
        for (int i = tid; i < 32 * 128; i += 256) {
            int kk = i >> 7, c = i & 127;
            sW[kk * 132 + c] = W[(size_t)(kt + kk) * 128 + c];
        }
        __syncthreads();
#pragma unroll 8
        for (int kk = 0; kk < 32; kk++) {
            float x0 = sXT[(kt + kk) * 33 + r0];
            float x1 = sXT[(kt + kk) * 33 + r0 + 1];
            const float* wr = &sW[kk * 132 + cx];
#pragma unroll
            for (int j = 0; j < 8; j++) {
                float w = wr[16 * j];
                acc0[j] += x0 * w;
                acc1[j] += x1 * w;
            }
        }
        __syncthreads();
    }

    // Reuse sXT storage as sH[32][132] (4224 floats each; GEMM reads are done)
    float* sH = sXT;
#pragma unroll
    for (int j = 0; j < 8; j++) {
        float bb = bias[cx + 16 * j];
        sH[(r0 + 0) * 132 + cx + 16 * j] = acc0[j] + bb;
        sH[(r0 + 1) * 132 + cx + 16 * j] = acc1[j] + bb;
    }
    __syncthreads();

    {
        int row = tid & 31, grp = tid >> 5;   // 8 groups x 16 cols
        float s = 0.f;
#pragma unroll
        for (int c = 0; c < 16; c++) {
            float v = sH[row * 132 + grp * 16 + c];
            s += v * v;
        }
        sPart[row * 8 + grp] = s;
    }
    __syncthreads();
    if (tid < 32) {
        float s = 0.f;
#pragma unroll
        for (int g = 0; g < 8; g++) s += sPart[tid * 8 + g];
        sRn[tid] = 1.0f / fmaxf(sqrtf(s), 1e-12f);
    }
    __syncthreads();

    float* oh = out_h  + ((size_t)b * N_ + row0) * H_;
    float* on = out_nh + ((size_t)b * N_ + row0) * H_;
    for (int i = tid; i < 32 * 128; i += 256) {
        int r = i >> 7, c = i & 127;
        float v = sH[r * 132 + c];
        oh[i] = v;
        on[i] = v * sRn[r];
    }
}

// ---------------------------------------------------------------------------
// Kernel 2: fused masked-cosine aggregation
//   out[b,p,:] = sum_q  ew[b,p,q] * (nh_p . nh_q) * h[b,q,:]   (+ optional relu)
// Block: 256 threads, 64 p-rows. Grid: (N/64, B). Dynamic smem ~130 KB.
// ---------------------------------------------------------------------------
#define SMEM_FLOATS (128*65 + 128*65 + 64*132 + 64*65 + 64*65)
#define SMEM_BYTES  (SMEM_FLOATS * 4)

__global__ __launch_bounds__(256, 1) void agg_kernel(
    const float* __restrict__ h, const float* __restrict__ nh,
    const float* __restrict__ ew, float* __restrict__ out, int do_relu)
{
    extern __shared__ float sm[];
    float* sPn = sm;                    // nhP^T [k][p], stride 65
    float* sQn = sPn + 128 * 65;        // nhQ^T [k][q], stride 65
    float* sQh = sQn + 128 * 65;        // hQ    [q][c], stride 132 (float4-aligned)
    float* sS  = sQh + 64 * 132;        // S     [q][p], stride 65
    float* sEw = sS  + 64 * 65;         // ew    [p][q], stride 65

    const int tid = threadIdx.x;
    const int b   = blockIdx.y;
    const int p0  = blockIdx.x * 64;

    const float* nhP = nh + ((size_t)b * N_ + p0) * H_;
    for (int i = tid; i < 64 * 128; i += 256) {
        int r = i >> 7, c = i & 127;
        sPn[c * 65 + r] = nhP[i];
    }

    const int cx = tid & 15;
    const int ry = tid >> 4;
    const int sp0 = ry * 4;          // stage A: p micro-rows
    const int sq0 = cx * 4;          // stage A: q micro-cols
    const int bc0 = cx * 8;          // stage B: output cols

    float acc[4][8];
#pragma unroll
    for (int i = 0; i < 4; i++)
#pragma unroll
        for (int j = 0; j < 8; j++) acc[i][j] = 0.f;

    const float* ewRow = ew + ((size_t)b * N_ + p0) * (size_t)N_;

    for (int q0 = 0; q0 < N_; q0 += 64) {
        const float* nhQ = nh + ((size_t)b * N_ + q0) * H_;
        const float* hQ  = h  + ((size_t)b * N_ + q0) * H_;

        __syncthreads();   // previous iteration fully consumed smem
        for (int i = tid; i < 64 * 128; i += 256) {
            int r = i >> 7, c = i & 127;
            sQn[c * 65 + r]  = nhQ[i];
            sQh[r * 132 + c] = hQ[i];
        }
        for (int i = tid; i < 64 * 64; i += 256) {
            int p = i >> 6, q = i & 63;
            sEw[p * 65 + q] = ewRow[(size_t)p * N_ + q0 + q];
        }
        __syncthreads();

        // ---- Stage A: S[p][q] = (nhP . nhQ) over k=128, then * ew ----
        float sa[4][4];
#pragma unroll
        for (int i = 0; i < 4; i++)
#pragma unroll
            for (int j = 0; j < 4; j++) sa[i][j] = 0.f;

#pragma unroll 4
        for (int k = 0; k < 128; k++) {
            float a0 = sPn[k * 65 + sp0 + 0];
            float a1 = sPn[k * 65 + sp0 + 1];
            float a2 = sPn[k * 65 + sp0 + 2];
            float a3 = sPn[k * 65 + sp0 + 3];
            float c0 = sQn[k * 65 + sq0 + 0];
            float c1 = sQn[k * 65 + sq0 + 1];
            float c2 = sQn[k * 65 + sq0 + 2];
            float c3 = sQn[k * 65 + sq0 + 3];
            sa[0][0] += a0 * c0; sa[0][1] += a0 * c1; sa[0][2] += a0 * c2; sa[0][3] += a0 * c3;
            sa[1][0] += a1 * c0; sa[1][1] += a1 * c1; sa[1][2] += a1 * c2; sa[1][3] += a1 * c3;
            sa[2][0] += a2 * c0; sa[2][1] += a2 * c1; sa[2][2] += a2 * c2; sa[2][3] += a2 * c3;
            sa[3][0] += a3 * c0; sa[3][1] += a3 * c1; sa[3][2] += a3 * c2; sa[3][3] += a3 * c3;
        }
#pragma unroll
        for (int i = 0; i < 4; i++)
#pragma unroll
            for (int j = 0; j < 4; j++)
                sS[(sq0 + j) * 65 + sp0 + i] =
                    sa[i][j] * sEw[(sp0 + i) * 65 + sq0 + j];
        __syncthreads();

        // ---- Stage B: O[p][c] += S[p][q] * hQ[q][c] over q=64 ----
#pragma unroll 4
        for (int q = 0; q < 64; q++) {
            float s0 = sS[q * 65 + sp0 + 0];
            float s1 = sS[q * 65 + sp0 + 1];
            float s2 = sS[q * 65 + sp0 + 2];
            float s3 = sS[q * 65 + sp0 + 3];
            float4 h0 = *(const float4*)&sQh[q * 132 + bc0];
            float4 h1 = *(const float4*)&sQh[q * 132 + bc0 + 4];
            acc[0][0] += s0 * h0.x; acc[0][1] += s0 * h0.y; acc[0][2] += s0 * h0.z; acc[0][3] += s0 * h0.w;
            acc[0][4] += s0 * h1.x; acc[0][5] += s0 * h1.y; acc[0][6] += s0 * h1.z; acc[0][7] += s0 * h1.w;
            acc[1][0] += s1 * h0.x; acc[1][1] += s1 * h0.y; acc[1][2] += s1 * h0.z; acc[1][3] += s1 * h0.w;
            acc[1][4] += s1 * h1.x; acc[1][5] += s1 * h1.y; acc[1][6] += s1 * h1.z; acc[1][7] += s1 * h1.w;
            acc[2][0] += s2 * h0.x; acc[2][1] += s2 * h0.y; acc[2][2] += s2 * h0.z; acc[2][3] += s2 * h0.w;
            acc[2][4] += s2 * h1.x; acc[2][5] += s2 * h1.y; acc[2][6] += s2 * h1.z; acc[2][7] += s2 * h1.w;
            acc[3][0] += s3 * h0.x; acc[3][1] += s3 * h0.y; acc[3][2] += s3 * h0.z; acc[3][3] += s3 * h0.w;
            acc[3][4] += s3 * h1.x; acc[3][5] += s3 * h1.y; acc[3][6] += s3 * h1.z; acc[3][7] += s3 * h1.w;
        }
    }

    float* op = out + ((size_t)b * N_ + p0) * H_;
#pragma unroll
    for (int i = 0; i < 4; i++) {
        int row = sp0 + i;
        float4 v0, v1;
        v0.x = acc[i][0]; v0.y = acc[i][1]; v0.z = acc[i][2]; v0.w = acc[i][3];
        v1.x = acc[i][4]; v1.y = acc[i][5]; v1.z = acc[i][6]; v1.w = acc[i][7];
        if (do_relu) {
            v0.x = fmaxf(v0.x, 0.f); v0.y = fmaxf(v0.y, 0.f);
            v0.z = fmaxf(v0.z, 0.f); v0.w = fmaxf(v0.w, 0.f);
            v1.x = fmaxf(v1.x, 0.f); v1.y = fmaxf(v1.y, 0.f);
            v1.z = fmaxf(v1.z, 0.f); v1.w = fmaxf(v1.w, 0.f);
        }
        *(float4*)&op[(size_t)row * 128 + bc0]     = v0;
        *(float4*)&op[(size_t)row * 128 + bc0 + 4] = v1;
    }
}

// ---------------------------------------------------------------------------
extern "C" void kernel_launch(void* const* d_in, const int* in_sizes, int n_in,
                              void* d_out, int out_size)
{
    (void)in_sizes; (void)n_in; (void)out_size;
    const float* x  = (const float*)d_in[0];
    const float* ew = (const float*)d_in[1];
    const float* Wl[3] = {(const float*)d_in[2], (const float*)d_in[4], (const float*)d_in[6]};
    const float* bl[3] = {(const float*)d_in[3], (const float*)d_in[5], (const float*)d_in[7]};
    float* out = (float*)d_out;

    void *pl, *pn, *pb;
    cudaGetSymbolAddress(&pl, g_lin);
    cudaGetSymbolAddress(&pn, g_nh);
    cudaGetSymbolAddress(&pb, g_buf);
    float* lin = (float*)pl;
    float* nhp = (float*)pn;
    float* buf = (float*)pb;

    cudaFuncSetAttribute(agg_kernel, cudaFuncAttributeMaxDynamicSharedMemorySize,
                         SMEM_BYTES);

    const float* cur = x;
    for (int l = 0; l < 3; l++) {
        lin_norm_kernel<<<dim3(N_ / 32, B_), 256>>>(cur, Wl[l], bl[l], lin, nhp);
        float* o = (l == 2) ? out : buf;
        agg_kernel<<<dim3(N_ / 64, B_), 256, SMEM_BYTES>>>(lin, nhp, ew, o,
                                                           (l < 2) ? 1 : 0);
        cur = buf;
    }
}

// round 5
// speedup vs baseline: 1.8937x; 1.8937x over previous
#include <cuda_runtime.h>

#define B_ 8
#define N_ 2048
#define H_ 128

// Scratch (device globals: allocation-free, graph-safe)
__device__ float g_lin[B_ * N_ * H_];   // h after linear (pre-aggregation)
__device__ float g_nh [B_ * N_ * H_];   // L2-normalized h
__device__ float g_buf[B_ * N_ * H_];   // aggregation output / next-layer input

// ---------------------------------------------------------------------------
// Kernel 1: h = in @ W + b ; nh = h / max(||h||, 1e-12)
// Block: 256 threads, 32 rows. Grid: (N/32, B).
// ---------------------------------------------------------------------------
__global__ __launch_bounds__(256) void lin_norm_kernel(
    const float* __restrict__ in, const float* __restrict__ W,
    const float* __restrict__ bias, float* __restrict__ out_h,
    float* __restrict__ out_nh)
{
    __shared__ float sXT[128 * 33];   // X tile transposed [k][r]
    __shared__ float sW[32 * 132];    // W chunk [kk][c]
    __shared__ float sPart[32 * 8];
    __shared__ float sRn[32];

    const int tid  = threadIdx.x;
    const int b    = blockIdx.y;
    const int row0 = blockIdx.x * 32;
    const float* X = in + ((size_t)b * N_ + row0) * H_;

    for (int i = tid; i < 32 * 128; i += 256) {
        int r = i >> 7, c = i & 127;
        sXT[c * 33 + r] = X[r * 128 + c];
    }
    __syncthreads();

    const int cx = tid & 15;
    const int ry = tid >> 4;
    const int r0 = ry * 2;

    float acc0[8], acc1[8];
#pragma unroll
    for (int j = 0; j < 8; j++) { acc0[j] = 0.f; acc1[j] = 0.f; }

    for (int kt = 0; kt < 128; kt += 32) {
        for (int i = tid; i < 32 * 128; i += 256) {
            int kk = i >> 7, c = i & 127;
            sW[kk * 132 + c] = W[(size_t)(kt + kk) * 128 + c];
        }
        __syncthreads();
#pragma unroll 8
        for (int kk = 0; kk < 32; kk++) {
            float x0 = sXT[(kt + kk) * 33 + r0];
            float x1 = sXT[(kt + kk) * 33 + r0 + 1];
            const float* wr = &sW[kk * 132 + cx];
#pragma unroll
            for (int j = 0; j < 8; j++) {
                float w = wr[16 * j];
                acc0[j] += x0 * w;
                acc1[j] += x1 * w;
            }
        }
        __syncthreads();
    }

    float* sH = sXT;
#pragma unroll
    for (int j = 0; j < 8; j++) {
        float bb = bias[cx + 16 * j];
        sH[(r0 + 0) * 132 + cx + 16 * j] = acc0[j] + bb;
        sH[(r0 + 1) * 132 + cx + 16 * j] = acc1[j] + bb;
    }
    __syncthreads();

    {
        int row = tid & 31, grp = tid >> 5;
        float s = 0.f;
#pragma unroll
        for (int c = 0; c < 16; c++) {
            float v = sH[row * 132 + grp * 16 + c];
            s += v * v;
        }
        sPart[row * 8 + grp] = s;
    }
    __syncthreads();
    if (tid < 32) {
        float s = 0.f;
#pragma unroll
        for (int g = 0; g < 8; g++) s += sPart[tid * 8 + g];
        sRn[tid] = 1.0f / fmaxf(sqrtf(s), 1e-12f);
    }
    __syncthreads();

    float* oh = out_h  + ((size_t)b * N_ + row0) * H_;
    float* on = out_nh + ((size_t)b * N_ + row0) * H_;
    for (int i = tid; i < 32 * 128; i += 256) {
        int r = i >> 7, c = i & 127;
        float v = sH[r * 132 + c];
        oh[i] = v;
        on[i] = v * sRn[r];
    }
}

// ---------------------------------------------------------------------------
// Kernel 2: fused masked-cosine aggregation (occupancy-optimized)
//   out[b,p,:] = sum_q  ew[b,p,q] * (nh_p . nh_q) * h[b,q,:]   (+ optional relu)
// Block: 256 threads, 64 p-rows. Grid: (N/64, B). smem ~101 KB -> 2 blocks/SM.
// ---------------------------------------------------------------------------
#define SPN_STRIDE 68
#define SQH_STRIDE 132
#define SMEM_FLOATS (128*SPN_STRIDE + 128*SPN_STRIDE + 64*SQH_STRIDE)
#define SMEM_BYTES  (SMEM_FLOATS * 4)

__global__ __launch_bounds__(256, 2) void agg_kernel(
    const float* __restrict__ h, const float* __restrict__ nh,
    const float* __restrict__ ew, float* __restrict__ out, int do_relu)
{
    extern __shared__ float sm[];
    float* sPn = sm;                         // nhP^T [k=128][p], stride 68 (16B-aligned f4)
    float* sQn = sPn + 128 * SPN_STRIDE;     // nhQ^T [k=128][q], stride 68
    float* sQh = sQn + 128 * SPN_STRIDE;     // hQ    [q=64][c],  stride 132
    float* sS  = sQn;                        // S [q=64][p] stride 68 — ALIASES sQn[0:4352]

    const int tid = threadIdx.x;
    const int b   = blockIdx.y;
    const int p0  = blockIdx.x * 64;

    const int cx  = tid & 15;
    const int ry  = tid >> 4;
    const int sp0 = ry * 4;          // stage A/B: p micro-rows
    const int sq0 = cx * 4;          // stage A: q micro-cols
    const int cc   = tid & 127;      // fill: column (k) index
    const int half = tid >> 7;       // fill: row-group selector

    // ---- fill sPn = nhP^T (coalesced scalar LDG, conflict-free STS.128) ----
    const float* nhP = nh + ((size_t)b * N_ + p0) * H_;
#pragma unroll
    for (int it = 0; it < 8; it++) {
        int r0 = half * 32 + it * 4;
        float v0 = nhP[(r0 + 0) * H_ + cc];
        float v1 = nhP[(r0 + 1) * H_ + cc];
        float v2 = nhP[(r0 + 2) * H_ + cc];
        float v3 = nhP[(r0 + 3) * H_ + cc];
        *(float4*)&sPn[cc * SPN_STRIDE + r0] = make_float4(v0, v1, v2, v3);
    }

    float acc[4][8];
#pragma unroll
    for (int i = 0; i < 4; i++)
#pragma unroll
        for (int j = 0; j < 8; j++) acc[i][j] = 0.f;

    const float* ewBase = ew + ((size_t)b * N_ + p0 + sp0) * (size_t)N_ + sq0;

    for (int q0 = 0; q0 < N_; q0 += 64) {
        const float* nhQ = nh + ((size_t)b * N_ + q0) * H_;
        const float* hQ  = h  + ((size_t)b * N_ + q0) * H_;

        __syncthreads();   // prev iter (stage B) fully consumed sS/sQh; sPn fill done

        // fill sQn = nhQ^T
#pragma unroll
        for (int it = 0; it < 8; it++) {
            int r0 = half * 32 + it * 4;
            float v0 = nhQ[(r0 + 0) * H_ + cc];
            float v1 = nhQ[(r0 + 1) * H_ + cc];
            float v2 = nhQ[(r0 + 2) * H_ + cc];
            float v3 = nhQ[(r0 + 3) * H_ + cc];
            *(float4*)&sQn[cc * SPN_STRIDE + r0] = make_float4(v0, v1, v2, v3);
        }
        // fill sQh = hQ (float4 copy)
#pragma unroll
        for (int it = 0; it < 8; it++) {
            int i = tid + it * 256;          // over 64*32 float4s
            int q = i >> 5, c4 = (i & 31) * 4;
            *(float4*)&sQh[q * SQH_STRIDE + c4] = *(const float4*)&hQ[q * H_ + c4];
        }

        // ew for this thread's 4x4 micro-tile, straight from gmem (coalesced f4)
        float ewv[4][4];
#pragma unroll
        for (int i = 0; i < 4; i++) {
            float4 e = *(const float4*)&ewBase[(size_t)i * N_ + q0];
            ewv[i][0] = e.x; ewv[i][1] = e.y; ewv[i][2] = e.z; ewv[i][3] = e.w;
        }
        __syncthreads();

        // ---- Stage A: sa[i][j] = nhP[sp0+i] . nhQ[sq0+j] over k=128 ----
        float sa[4][4];
#pragma unroll
        for (int i = 0; i < 4; i++)
#pragma unroll
            for (int j = 0; j < 4; j++) sa[i][j] = 0.f;

#pragma unroll 8
        for (int k = 0; k < 128; k++) {
            float4 a = *(const float4*)&sPn[k * SPN_STRIDE + sp0];
            float4 c = *(const float4*)&sQn[k * SPN_STRIDE + sq0];
            sa[0][0] += a.x * c.x; sa[0][1] += a.x * c.y; sa[0][2] += a.x * c.z; sa[0][3] += a.x * c.w;
            sa[1][0] += a.y * c.x; sa[1][1] += a.y * c.y; sa[1][2] += a.y * c.z; sa[1][3] += a.y * c.w;
            sa[2][0] += a.z * c.x; sa[2][1] += a.z * c.y; sa[2][2] += a.z * c.z; sa[2][3] += a.z * c.w;
            sa[3][0] += a.w * c.x; sa[3][1] += a.w * c.y; sa[3][2] += a.w * c.z; sa[3][3] += a.w * c.w;
        }
        __syncthreads();   // all sQn reads done before aliased sS writes

        // ---- write S[q][p] = sa * ew (float4 over p) ----
#pragma unroll
        for (int j = 0; j < 4; j++) {
            float4 v = make_float4(sa[0][j] * ewv[0][j], sa[1][j] * ewv[1][j],
                                   sa[2][j] * ewv[2][j], sa[3][j] * ewv[3][j]);
            *(float4*)&sS[(sq0 + j) * SPN_STRIDE + sp0] = v;
        }
        __syncthreads();

        // ---- Stage B: O[p][c] += S[p][q] * hQ[q][c], cols c = 2cx + 32j + t ----
#pragma unroll 4
        for (int q = 0; q < 64; q++) {
            float4 s = *(const float4*)&sS[q * SPN_STRIDE + sp0];
            float2 h0 = *(const float2*)&sQh[q * SQH_STRIDE + 2 * cx];
            float2 h1 = *(const float2*)&sQh[q * SQH_STRIDE + 2 * cx + 32];
            float2 h2 = *(const float2*)&sQh[q * SQH_STRIDE + 2 * cx + 64];
            float2 h3 = *(const float2*)&sQh[q * SQH_STRIDE + 2 * cx + 96];
            acc[0][0] += s.x * h0.x; acc[0][1] += s.x * h0.y;
            acc[0][2] += s.x * h1.x; acc[0][3] += s.x * h1.y;
            acc[0][4] += s.x * h2.x; acc[0][5] += s.x * h2.y;
            acc[0][6] += s.x * h3.x; acc[0][7] += s.x * h3.y;
            acc[1][0] += s.y * h0.x; acc[1][1] += s.y * h0.y;
            acc[1][2] += s.y * h1.x; acc[1][3] += s.y * h1.y;
            acc[1][4] += s.y * h2.x; acc[1][5] += s.y * h2.y;
            acc[1][6] += s.y * h3.x; acc[1][7] += s.y * h3.y;
            acc[2][0] += s.z * h0.x; acc[2][1] += s.z * h0.y;
            acc[2][2] += s.z * h1.x; acc[2][3] += s.z * h1.y;
            acc[2][4] += s.z * h2.x; acc[2][5] += s.z * h2.y;
            acc[2][6] += s.z * h3.x; acc[2][7] += s.z * h3.y;
            acc[3][0] += s.w * h0.x; acc[3][1] += s.w * h0.y;
            acc[3][2] += s.w * h1.x; acc[3][3] += s.w * h1.y;
            acc[3][4] += s.w * h2.x; acc[3][5] += s.w * h2.y;
            acc[3][6] += s.w * h3.x; acc[3][7] += s.w * h3.y;
        }
    }

    // ---- epilogue: float2 stores, cols 2cx + 32j ----
#pragma unroll
    for (int i = 0; i < 4; i++) {
        float* rowp = out + ((size_t)b * N_ + p0 + sp0 + i) * H_;
#pragma unroll
        for (int j = 0; j < 4; j++) {
            float2 v;
            v.x = acc[i][2 * j + 0];
            v.y = acc[i][2 * j + 1];
            if (do_relu) { v.x = fmaxf(v.x, 0.f); v.y = fmaxf(v.y, 0.f); }
            *(float2*)&rowp[32 * j + 2 * cx] = v;
        }
    }
}

// ---------------------------------------------------------------------------
extern "C" void kernel_launch(void* const* d_in, const int* in_sizes, int n_in,
                              void* d_out, int out_size)
{
    (void)in_sizes; (void)n_in; (void)out_size;
    const float* x  = (const float*)d_in[0];
    const float* ew = (const float*)d_in[1];
    const float* Wl[3] = {(const float*)d_in[2], (const float*)d_in[4], (const float*)d_in[6]};
    const float* bl[3] = {(const float*)d_in[3], (const float*)d_in[5], (const float*)d_in[7]};
    float* out = (float*)d_out;

    void *pl, *pn, *pb;
    cudaGetSymbolAddress(&pl, g_lin);
    cudaGetSymbolAddress(&pn, g_nh);
    cudaGetSymbolAddress(&pb, g_buf);
    float* lin = (float*)pl;
    float* nhp = (float*)pn;
    float* buf = (float*)pb;

    cudaFuncSetAttribute(agg_kernel, cudaFuncAttributeMaxDynamicSharedMemorySize,
                         SMEM_BYTES);

    const float* cur = x;
    for (int l = 0; l < 3; l++) {
        lin_norm_kernel<<<dim3(N_ / 32, B_), 256>>>(cur, Wl[l], bl[l], lin, nhp);
        float* o = (l == 2) ? out : buf;
        agg_kernel<<<dim3(N_ / 64, B_), 256, SMEM_BYTES>>>(lin, nhp, ew, o,
                                                           (l < 2) ? 1 : 0);
        cur = buf;
    }
}

// round 16
// speedup vs baseline: 3.2912x; 1.7380x over previous
#include <cuda_runtime.h>
#include <cuda_bf16.h>
#include <cstdint>

#define B_ 8
#define N_ 2048
#define H_ 128

// bf16 hi/lo split operands (produced by lin_norm, consumed by agg MMA)
__device__ __nv_bfloat16 g_nh_hi[B_ * N_ * H_];   // nh row-major  [b][n][k]
__device__ __nv_bfloat16 g_nh_lo[B_ * N_ * H_];
__device__ __nv_bfloat16 g_hT_hi[B_ * H_ * N_];   // h transposed  [b][c][n]
__device__ __nv_bfloat16 g_hT_lo[B_ * H_ * N_];
__device__ float g_buf[B_ * N_ * H_];             // layer output / next input

__device__ __forceinline__ void split_bf(float v, __nv_bfloat16& h, __nv_bfloat16& l) {
    h = __float2bfloat16_rn(v);
    l = __float2bfloat16_rn(v - __bfloat162float(h));
}
__device__ __forceinline__ uint32_t pack_bf2(__nv_bfloat16 a, __nv_bfloat16 b) {
    __nv_bfloat162 t; t.x = a; t.y = b;
    return *reinterpret_cast<uint32_t*>(&t);
}

// mma.sync m16n8k16 bf16, fp32 accumulate (sm_80+ baseline PTX)
#define MMA16816(C, a0, a1, a2, a3, b0, b1)                                      \
    asm volatile("mma.sync.aligned.m16n8k16.row.col.f32.bf16.bf16.f32 "          \
                 "{%0,%1,%2,%3}, {%4,%5,%6,%7}, {%8,%9}, {%0,%1,%2,%3};"         \
                 : "+f"((C)[0]), "+f"((C)[1]), "+f"((C)[2]), "+f"((C)[3])        \
                 : "r"(a0), "r"(a1), "r"(a2), "r"(a3), "r"(b0), "r"(b1))

// ===========================================================================
// Kernel 1: h = in @ W + b ; emit nh hi/lo (row-major) and h hi/lo (transposed)
// ===========================================================================
__global__ __launch_bounds__(256) void lin_norm_kernel(
    const float* __restrict__ in, const float* __restrict__ W,
    const float* __restrict__ bias,
    __nv_bfloat16* __restrict__ nh_hi, __nv_bfloat16* __restrict__ nh_lo,
    __nv_bfloat16* __restrict__ hT_hi, __nv_bfloat16* __restrict__ hT_lo)
{
    __shared__ float sXT[128 * 33];
    __shared__ float sW[32 * 132];
    __shared__ float sPart[32 * 8];
    __shared__ float sRn[32];

    const int tid  = threadIdx.x;
    const int b    = blockIdx.y;
    const int row0 = blockIdx.x * 32;
    const float* X = in + ((size_t)b * N_ + row0) * H_;

    for (int i = tid; i < 32 * 128; i += 256) {
        int r = i >> 7, c = i & 127;
        sXT[c * 33 + r] = X[r * 128 + c];
    }
    __syncthreads();

    const int cx = tid & 15, ry = tid >> 4, r0 = ry * 2;
    float acc0[8], acc1[8];
#pragma unroll
    for (int j = 0; j < 8; j++) { acc0[j] = 0.f; acc1[j] = 0.f; }

    for (int kt = 0; kt < 128; kt += 32) {
        for (int i = tid; i < 32 * 128; i += 256) {
            int kk = i >> 7, c = i & 127;
            sW[kk * 132 + c] = W[(size_t)(kt + kk) * 128 + c];
        }
        __syncthreads();
#pragma unroll 8
        for (int kk = 0; kk < 32; kk++) {
            float x0 = sXT[(kt + kk) * 33 + r0];
            float x1 = sXT[(kt + kk) * 33 + r0 + 1];
            const float* wr = &sW[kk * 132 + cx];
#pragma unroll
            for (int j = 0; j < 8; j++) {
                float w = wr[16 * j];
                acc0[j] += x0 * w;
                acc1[j] += x1 * w;
            }
        }
        __syncthreads();
    }

    float* sH = sXT;
#pragma unroll
    for (int j = 0; j < 8; j++) {
        float bb = bias[cx + 16 * j];
        sH[(r0 + 0) * 132 + cx + 16 * j] = acc0[j] + bb;
        sH[(r0 + 1) * 132 + cx + 16 * j] = acc1[j] + bb;
    }
    __syncthreads();

    {
        int row = tid & 31, grp = tid >> 5;
        float s = 0.f;
#pragma unroll
        for (int c = 0; c < 16; c++) {
            float v = sH[row * 132 + grp * 16 + c];
            s += v * v;
        }
        sPart[row * 8 + grp] = s;
    }
    __syncthreads();
    if (tid < 32) {
        float s = 0.f;
#pragma unroll
        for (int g = 0; g < 8; g++) s += sPart[tid * 8 + g];
        sRn[tid] = 1.0f / fmaxf(sqrtf(s), 1e-12f);
    }
    __syncthreads();

    // nh hi/lo row-major
    const size_t nb = ((size_t)b * N_ + row0) * H_;
    for (int i = tid; i < 32 * 128; i += 256) {
        int r = i >> 7, c = i & 127;
        float v = sH[r * 132 + c] * sRn[r];
        __nv_bfloat16 h, l; split_bf(v, h, l);
        nh_hi[nb + i] = h;
        nh_lo[nb + i] = l;
    }
    // hT hi/lo transposed: thread -> (c = tid>>1, rows (tid&1)*16 .. +15)
    {
        int c  = tid >> 1;
        int rh = (tid & 1) * 16;
        uint32_t* dh = (uint32_t*)hT_hi + (((size_t)b * H_ + c) * N_ + row0 + rh) / 2;
        uint32_t* dl = (uint32_t*)hT_lo + (((size_t)b * H_ + c) * N_ + row0 + rh) / 2;
#pragma unroll
        for (int j = 0; j < 8; j++) {
            float v0 = sH[(rh + 2 * j + 0) * 132 + c];
            float v1 = sH[(rh + 2 * j + 1) * 132 + c];
            __nv_bfloat16 h0, l0, h1, l1;
            split_bf(v0, h0, l0);
            split_bf(v1, h1, l1);
            dh[j] = pack_bf2(h0, h1);
            dl[j] = pack_bf2(l0, l1);
        }
    }
}

// ===========================================================================
// Kernel 2: warp-MMA fused aggregation. CTA = 128 p-rows, 8 warps (16 rows ea),
// q-tiles of 64. Hi/lo bf16 split, 3 mma passes per contraction.
// ===========================================================================
// smem byte offsets (bf16 tiles; row strides padded for conflict-free LDS.32)
#define OFF_PN_HI 0               // nhP [128][136]
#define OFF_PN_LO 34816
#define OFF_QN_HI 69632           // nhQ [64][136]
#define OFF_QN_LO 87040
#define OFF_HT_HI 104448          // hT  [128][72]
#define OFF_HT_LO 122880
#define AGG_SMEM  141312
#define PNW 68                    // word stride nhP/nhQ rows
#define HTW 36                    // word stride hT rows

__global__ __launch_bounds__(256, 1) void agg_mma_kernel(
    const __nv_bfloat16* __restrict__ nh_hi, const __nv_bfloat16* __restrict__ nh_lo,
    const __nv_bfloat16* __restrict__ hT_hi, const __nv_bfloat16* __restrict__ hT_lo,
    const float* __restrict__ ew, float* __restrict__ out, int do_relu)
{
    extern __shared__ char smem[];
    uint32_t* sPnH = (uint32_t*)(smem + OFF_PN_HI);
    uint32_t* sPnL = (uint32_t*)(smem + OFF_PN_LO);
    uint32_t* sQnH = (uint32_t*)(smem + OFF_QN_HI);
    uint32_t* sQnL = (uint32_t*)(smem + OFF_QN_LO);
    uint32_t* sHTH = (uint32_t*)(smem + OFF_HT_HI);
    uint32_t* sHTL = (uint32_t*)(smem + OFF_HT_LO);

    const int tid = threadIdx.x;
    const int wid = tid >> 5, lane = tid & 31;
    const int lr = lane >> 2, lc = lane & 3;
    const int b = blockIdx.y, p0 = blockIdx.x * 128;
    const int m0 = wid * 16;

    // ---- fill nhP [128][136] hi/lo (once) ----
    {
        const uint4* sh = (const uint4*)(nh_hi + ((size_t)b * N_ + p0) * H_);
        const uint4* sl = (const uint4*)(nh_lo + ((size_t)b * N_ + p0) * H_);
        for (int i = tid; i < 2048; i += 256) {
            int r = i >> 4, j = i & 15;
            *(uint4*)(smem + OFF_PN_HI + r * 272 + j * 16) = sh[i];
            *(uint4*)(smem + OFF_PN_LO + r * 272 + j * 16) = sl[i];
        }
    }

    float Oc[16][4];
#pragma unroll
    for (int i = 0; i < 16; i++)
#pragma unroll
        for (int j = 0; j < 4; j++) Oc[i][j] = 0.f;

    const float* ewRow = ew + ((size_t)b * N_ + p0 + m0 + lr) * (size_t)N_;

    for (int q0 = 0; q0 < N_; q0 += 64) {
        __syncthreads();   // previous tile's smem reads complete
        // ---- fills: nhQ [64][136] hi/lo, hT [128][72] hi/lo ----
        {
            const uint4* sh = (const uint4*)(nh_hi + ((size_t)b * N_ + q0) * H_);
            const uint4* sl = (const uint4*)(nh_lo + ((size_t)b * N_ + q0) * H_);
            for (int i = tid; i < 1024; i += 256) {
                int r = i >> 4, j = i & 15;
                *(uint4*)(smem + OFF_QN_HI + r * 272 + j * 16) = sh[i];
                *(uint4*)(smem + OFF_QN_LO + r * 272 + j * 16) = sl[i];
            }
            // hT tile: 128 cols x 64 q = 8 uint4 per col row (FIXED: full row fill)
            for (int i = tid; i < 1024; i += 256) {
                int c = i >> 3, j = i & 7;
                const uint4* rh = (const uint4*)(hT_hi + ((size_t)b * H_ + c) * N_ + q0);
                const uint4* rl = (const uint4*)(hT_lo + ((size_t)b * H_ + c) * N_ + q0);
                *(uint4*)(smem + OFF_HT_HI + c * 144 + j * 16) = rh[j];
                *(uint4*)(smem + OFF_HT_LO + c * 144 + j * 16) = rl[j];
            }
        }
        __syncthreads();

        // ---- Stage A: S[16x64] per warp = nhP . nhQ^T, 3 split passes ----
        float Sc[8][4];
#pragma unroll
        for (int i = 0; i < 8; i++)
#pragma unroll
            for (int j = 0; j < 4; j++) Sc[i][j] = 0.f;

#pragma unroll
        for (int kb = 0; kb < 8; kb++) {
            const int aw = (m0 + lr) * PNW + kb * 8 + lc;
            uint32_t ah0 = sPnH[aw],           ah1 = sPnH[aw + 8 * PNW];
            uint32_t ah2 = sPnH[aw + 4],       ah3 = sPnH[aw + 8 * PNW + 4];
            uint32_t al0 = sPnL[aw],           al1 = sPnL[aw + 8 * PNW];
            uint32_t al2 = sPnL[aw + 4],       al3 = sPnL[aw + 8 * PNW + 4];
#pragma unroll
            for (int nb = 0; nb < 8; nb++) {
                const int bw = (nb * 8 + lr) * PNW + kb * 8 + lc;
                uint32_t bh0 = sQnH[bw], bh1 = sQnH[bw + 4];
                uint32_t bl0 = sQnL[bw], bl1 = sQnL[bw + 4];
                MMA16816(Sc[nb], ah0, ah1, ah2, ah3, bh0, bh1);
                MMA16816(Sc[nb], ah0, ah1, ah2, ah3, bl0, bl1);
                MMA16816(Sc[nb], al0, al1, al2, al3, bh0, bh1);
            }
        }

        // ---- ew mask + split: C fragments -> A fragments (registers only) ----
        uint32_t Ah[4][4], Al[4][4];
#pragma unroll
        for (int j = 0; j < 8; j++) {
            float2 e0 = *(const float2*)(ewRow + q0 + 8 * j + 2 * lc);
            float2 e1 = *(const float2*)(ewRow + 8 * (size_t)N_ + q0 + 8 * j + 2 * lc);
            float s0 = Sc[j][0] * e0.x, s1 = Sc[j][1] * e0.y;
            float s2 = Sc[j][2] * e1.x, s3 = Sc[j][3] * e1.y;
            __nv_bfloat16 h0, l0, h1, l1, h2, l2, h3, l3;
            split_bf(s0, h0, l0); split_bf(s1, h1, l1);
            split_bf(s2, h2, l2); split_bf(s3, h3, l3);
            int t = j >> 1, half = (j & 1) * 2;
            Ah[t][half + 0] = pack_bf2(h0, h1);
            Ah[t][half + 1] = pack_bf2(h2, h3);
            Al[t][half + 0] = pack_bf2(l0, l1);
            Al[t][half + 1] = pack_bf2(l2, l3);
        }

        // ---- Stage B: O[16x128] += S . hQ (B from hT, k = q), 3 passes ----
#pragma unroll
        for (int qb = 0; qb < 4; qb++) {
#pragma unroll
            for (int nb = 0; nb < 16; nb++) {
                const int bw = (nb * 8 + lr) * HTW + qb * 8 + lc;
                uint32_t bh0 = sHTH[bw], bh1 = sHTH[bw + 4];
                uint32_t bl0 = sHTL[bw], bl1 = sHTL[bw + 4];
                MMA16816(Oc[nb], Ah[qb][0], Ah[qb][1], Ah[qb][2], Ah[qb][3], bh0, bh1);
                MMA16816(Oc[nb], Ah[qb][0], Ah[qb][1], Ah[qb][2], Ah[qb][3], bl0, bl1);
                MMA16816(Oc[nb], Al[qb][0], Al[qb][1], Al[qb][2], Al[qb][3], bh0, bh1);
            }
        }
    }

    // ---- epilogue: fragment rows m0+lr and m0+lr+8 ----
    float* orow0 = out + ((size_t)b * N_ + p0 + m0 + lr) * H_;
    float* orow8 = orow0 + 8 * H_;
#pragma unroll
    for (int nb = 0; nb < 16; nb++) {
        float2 v0, v1;
        v0.x = Oc[nb][0]; v0.y = Oc[nb][1];
        v1.x = Oc[nb][2]; v1.y = Oc[nb][3];
        if (do_relu) {
            v0.x = fmaxf(v0.x, 0.f); v0.y = fmaxf(v0.y, 0.f);
            v1.x = fmaxf(v1.x, 0.f); v1.y = fmaxf(v1.y, 0.f);
        }
        *(float2*)&orow0[nb * 8 + 2 * lc] = v0;
        *(float2*)&orow8[nb * 8 + 2 * lc] = v1;
    }
}

// ===========================================================================
extern "C" void kernel_launch(void* const* d_in, const int* in_sizes, int n_in,
                              void* d_out, int out_size)
{
    (void)in_sizes; (void)n_in; (void)out_size;
    const float* x  = (const float*)d_in[0];
    const float* ew = (const float*)d_in[1];
    const float* Wl[3] = {(const float*)d_in[2], (const float*)d_in[4], (const float*)d_in[6]};
    const float* bl[3] = {(const float*)d_in[3], (const float*)d_in[5], (const float*)d_in[7]};
    float* out = (float*)d_out;

    void *pnh, *pnl, *pth, *ptl, *pb;
    cudaGetSymbolAddress(&pnh, g_nh_hi);
    cudaGetSymbolAddress(&pnl, g_nh_lo);
    cudaGetSymbolAddress(&pth, g_hT_hi);
    cudaGetSymbolAddress(&ptl, g_hT_lo);
    cudaGetSymbolAddress(&pb,  g_buf);
    __nv_bfloat16* nh_hi = (__nv_bfloat16*)pnh;
    __nv_bfloat16* nh_lo = (__nv_bfloat16*)pnl;
    __nv_bfloat16* hT_hi = (__nv_bfloat16*)pth;
    __nv_bfloat16* hT_lo = (__nv_bfloat16*)ptl;
    float* buf = (float*)pb;

    cudaFuncSetAttribute(agg_mma_kernel,
                         cudaFuncAttributeMaxDynamicSharedMemorySize, AGG_SMEM);

    const float* cur = x;
    for (int l = 0; l < 3; l++) {
        lin_norm_kernel<<<dim3(N_ / 32, B_), 256>>>(cur, Wl[l], bl[l],
                                                    nh_hi, nh_lo, hT_hi, hT_lo);
        float* o = (l == 2) ? out : buf;
        agg_mma_kernel<<<dim3(N_ / 128, B_), 256, AGG_SMEM>>>(
            nh_hi, nh_lo, hT_hi, hT_lo, ew, o, (l < 2) ? 1 : 0);
        cur = buf;
    }
}

// round 17
// speedup vs baseline: 4.1334x; 1.2559x over previous
#include <cuda_runtime.h>
#include <cuda_bf16.h>
#include <cstdint>

#define B_ 8
#define N_ 2048
#define H_ 128

// bf16 hi/lo split operands (produced by lin_norm, consumed by agg MMA)
__device__ __nv_bfloat16 g_nh_hi[B_ * N_ * H_];   // nh row-major  [b][n][k]
__device__ __nv_bfloat16 g_nh_lo[B_ * N_ * H_];
__device__ __nv_bfloat16 g_hT_hi[B_ * H_ * N_];   // h transposed  [b][c][n]
__device__ __nv_bfloat16 g_hT_lo[B_ * H_ * N_];
__device__ float g_buf[B_ * N_ * H_];             // layer output / next input

__device__ __forceinline__ void split_bf(float v, __nv_bfloat16& h, __nv_bfloat16& l) {
    h = __float2bfloat16_rn(v);
    l = __float2bfloat16_rn(v - __bfloat162float(h));
}
__device__ __forceinline__ uint32_t pack_bf2(__nv_bfloat16 a, __nv_bfloat16 b) {
    __nv_bfloat162 t; t.x = a; t.y = b;
    return *reinterpret_cast<uint32_t*>(&t);
}

// mma.sync m16n8k16 bf16, fp32 accumulate (sm_80+ baseline PTX)
#define MMA16816(C, a0, a1, a2, a3, b0, b1)                                      \
    asm volatile("mma.sync.aligned.m16n8k16.row.col.f32.bf16.bf16.f32 "          \
                 "{%0,%1,%2,%3}, {%4,%5,%6,%7}, {%8,%9}, {%0,%1,%2,%3};"         \
                 : "+f"((C)[0]), "+f"((C)[1]), "+f"((C)[2]), "+f"((C)[3])        \
                 : "r"(a0), "r"(a1), "r"(a2), "r"(a3), "r"(b0), "r"(b1))

// ===========================================================================
// Kernel 1: h = in @ W + b ; emit nh hi/lo (row-major) and h hi/lo (transposed)
// ===========================================================================
__global__ __launch_bounds__(256) void lin_norm_kernel(
    const float* __restrict__ in, const float* __restrict__ W,
    const float* __restrict__ bias,
    __nv_bfloat16* __restrict__ nh_hi, __nv_bfloat16* __restrict__ nh_lo,
    __nv_bfloat16* __restrict__ hT_hi, __nv_bfloat16* __restrict__ hT_lo)
{
    __shared__ float sXT[128 * 33];
    __shared__ float sW[32 * 132];
    __shared__ float sPart[32 * 8];
    __shared__ float sRn[32];

    const int tid  = threadIdx.x;
    const int b    = blockIdx.y;
    const int row0 = blockIdx.x * 32;
    const float* X = in + ((size_t)b * N_ + row0) * H_;

    for (int i = tid; i < 32 * 128; i += 256) {
        int r = i >> 7, c = i & 127;
        sXT[c * 33 + r] = X[r * 128 + c];
    }
    __syncthreads();

    const int cx = tid & 15, ry = tid >> 4, r0 = ry * 2;
    float acc0[8], acc1[8];
#pragma unroll
    for (int j = 0; j < 8; j++) { acc0[j] = 0.f; acc1[j] = 0.f; }

    for (int kt = 0; kt < 128; kt += 32) {
        for (int i = tid; i < 32 * 128; i += 256) {
            int kk = i >> 7, c = i & 127;
            sW[kk * 132 + c] = W[(size_t)(kt + kk) * 128 + c];
        }
        __syncthreads();
#pragma unroll 8
        for (int kk = 0; kk < 32; kk++) {
            float x0 = sXT[(kt + kk) * 33 + r0];
            float x1 = sXT[(kt + kk) * 33 + r0 + 1];
            const float* wr = &sW[kk * 132 + cx];
#pragma unroll
            for (int j = 0; j < 8; j++) {
                float w = wr[16 * j];
                acc0[j] += x0 * w;
                acc1[j] += x1 * w;
            }
        }
        __syncthreads();
    }

    float* sH = sXT;
#pragma unroll
    for (int j = 0; j < 8; j++) {
        float bb = bias[cx + 16 * j];
        sH[(r0 + 0) * 132 + cx + 16 * j] = acc0[j] + bb;
        sH[(r0 + 1) * 132 + cx + 16 * j] = acc1[j] + bb;
    }
    __syncthreads();

    {
        int row = tid & 31, grp = tid >> 5;
        float s = 0.f;
#pragma unroll
        for (int c = 0; c < 16; c++) {
            float v = sH[row * 132 + grp * 16 + c];
            s += v * v;
        }
        sPart[row * 8 + grp] = s;
    }
    __syncthreads();
    if (tid < 32) {
        float s = 0.f;
#pragma unroll
        for (int g = 0; g < 8; g++) s += sPart[tid * 8 + g];
        sRn[tid] = 1.0f / fmaxf(sqrtf(s), 1e-12f);
    }
    __syncthreads();

    // nh hi/lo row-major
    const size_t nb = ((size_t)b * N_ + row0) * H_;
    for (int i = tid; i < 32 * 128; i += 256) {
        int r = i >> 7, c = i & 127;
        float v = sH[r * 132 + c] * sRn[r];
        __nv_bfloat16 h, l; split_bf(v, h, l);
        nh_hi[nb + i] = h;
        nh_lo[nb + i] = l;
    }
    // hT hi/lo transposed: thread -> (c = tid>>1, rows (tid&1)*16 .. +15)
    {
        int c  = tid >> 1;
        int rh = (tid & 1) * 16;
        uint32_t* dh = (uint32_t*)hT_hi + (((size_t)b * H_ + c) * N_ + row0 + rh) / 2;
        uint32_t* dl = (uint32_t*)hT_lo + (((size_t)b * H_ + c) * N_ + row0 + rh) / 2;
#pragma unroll
        for (int j = 0; j < 8; j++) {
            float v0 = sH[(rh + 2 * j + 0) * 132 + c];
            float v1 = sH[(rh + 2 * j + 1) * 132 + c];
            __nv_bfloat16 h0, l0, h1, l1;
            split_bf(v0, h0, l0);
            split_bf(v1, h1, l1);
            dh[j] = pack_bf2(h0, h1);
            dl[j] = pack_bf2(l0, l1);
        }
    }
}

// ===========================================================================
// Kernel 2: warp-MMA fused aggregation. CTA = 64 p-rows, 4 warps (16 rows ea),
// q-tiles of 64. Hi/lo bf16 split, 3 mma passes per contraction.
// 104 KB smem -> 2 CTAs/SM: independent CTAs overlap fill & MMA phases.
// ===========================================================================
// smem byte offsets (bf16 tiles; row strides padded for conflict-free LDS.32)
#define OFF_PN_HI 0               // nhP [64][136]
#define OFF_PN_LO 17408
#define OFF_QN_HI 34816           // nhQ [64][136]
#define OFF_QN_LO 52224
#define OFF_HT_HI 69632           // hT  [128][72]
#define OFF_HT_LO 88064
#define AGG_SMEM  106496
#define PNW 68                    // word stride nhP/nhQ rows
#define HTW 36                    // word stride hT rows

__global__ __launch_bounds__(128, 2) void agg_mma_kernel(
    const __nv_bfloat16* __restrict__ nh_hi, const __nv_bfloat16* __restrict__ nh_lo,
    const __nv_bfloat16* __restrict__ hT_hi, const __nv_bfloat16* __restrict__ hT_lo,
    const float* __restrict__ ew, float* __restrict__ out, int do_relu)
{
    extern __shared__ char smem[];
    uint32_t* sPnH = (uint32_t*)(smem + OFF_PN_HI);
    uint32_t* sPnL = (uint32_t*)(smem + OFF_PN_LO);
    uint32_t* sQnH = (uint32_t*)(smem + OFF_QN_HI);
    uint32_t* sQnL = (uint32_t*)(smem + OFF_QN_LO);
    uint32_t* sHTH = (uint32_t*)(smem + OFF_HT_HI);
    uint32_t* sHTL = (uint32_t*)(smem + OFF_HT_LO);

    const int tid = threadIdx.x;
    const int wid = tid >> 5, lane = tid & 31;
    const int lr = lane >> 2, lc = lane & 3;
    const int b = blockIdx.y, p0 = blockIdx.x * 64;
    const int m0 = wid * 16;

    // ---- fill nhP [64][136] hi/lo (once) ----
    {
        const uint4* sh = (const uint4*)(nh_hi + ((size_t)b * N_ + p0) * H_);
        const uint4* sl = (const uint4*)(nh_lo + ((size_t)b * N_ + p0) * H_);
#pragma unroll
        for (int it = 0; it < 8; it++) {
            int i = tid + it * 128;
            int r = i >> 4, j = i & 15;
            *(uint4*)(smem + OFF_PN_HI + r * 272 + j * 16) = sh[i];
            *(uint4*)(smem + OFF_PN_LO + r * 272 + j * 16) = sl[i];
        }
    }

    float Oc[16][4];
#pragma unroll
    for (int i = 0; i < 16; i++)
#pragma unroll
        for (int j = 0; j < 4; j++) Oc[i][j] = 0.f;

    const float* ewRow = ew + ((size_t)b * N_ + p0 + m0 + lr) * (size_t)N_;

    for (int q0 = 0; q0 < N_; q0 += 64) {
        __syncthreads();   // previous tile's smem reads complete
        // ---- fills: nhQ [64][136] hi/lo, hT [128][72] hi/lo ----
        {
            const uint4* sh = (const uint4*)(nh_hi + ((size_t)b * N_ + q0) * H_);
            const uint4* sl = (const uint4*)(nh_lo + ((size_t)b * N_ + q0) * H_);
#pragma unroll
            for (int it = 0; it < 8; it++) {
                int i = tid + it * 128;
                int r = i >> 4, j = i & 15;
                *(uint4*)(smem + OFF_QN_HI + r * 272 + j * 16) = sh[i];
                *(uint4*)(smem + OFF_QN_LO + r * 272 + j * 16) = sl[i];
            }
#pragma unroll
            for (int it = 0; it < 8; it++) {
                int i = tid + it * 128;
                int c = i >> 3, j = i & 7;
                const uint4* rh = (const uint4*)(hT_hi + ((size_t)b * H_ + c) * N_ + q0);
                const uint4* rl = (const uint4*)(hT_lo + ((size_t)b * H_ + c) * N_ + q0);
                *(uint4*)(smem + OFF_HT_HI + c * 144 + j * 16) = rh[j];
                *(uint4*)(smem + OFF_HT_LO + c * 144 + j * 16) = rl[j];
            }
        }
        __syncthreads();

        // ---- Stage A: S[16x64] per warp = nhP . nhQ^T, 3 split passes ----
        float Sc[8][4];
#pragma unroll
        for (int i = 0; i < 8; i++)
#pragma unroll
            for (int j = 0; j < 4; j++) Sc[i][j] = 0.f;

#pragma unroll
        for (int kb = 0; kb < 8; kb++) {
            const int aw = (m0 + lr) * PNW + kb * 8 + lc;
            uint32_t ah0 = sPnH[aw],           ah1 = sPnH[aw + 8 * PNW];
            uint32_t ah2 = sPnH[aw + 4],       ah3 = sPnH[aw + 8 * PNW + 4];
            uint32_t al0 = sPnL[aw],           al1 = sPnL[aw + 8 * PNW];
            uint32_t al2 = sPnL[aw + 4],       al3 = sPnL[aw + 8 * PNW + 4];
#pragma unroll
            for (int nb = 0; nb < 8; nb++) {
                const int bw = (nb * 8 + lr) * PNW + kb * 8 + lc;
                uint32_t bh0 = sQnH[bw], bh1 = sQnH[bw + 4];
                uint32_t bl0 = sQnL[bw], bl1 = sQnL[bw + 4];
                MMA16816(Sc[nb], ah0, ah1, ah2, ah3, bh0, bh1);
                MMA16816(Sc[nb], ah0, ah1, ah2, ah3, bl0, bl1);
                MMA16816(Sc[nb], al0, al1, al2, al3, bh0, bh1);
            }
        }

        // ---- ew mask + split: C fragments -> A fragments (registers only) ----
        uint32_t Ah[4][4], Al[4][4];
#pragma unroll
        for (int j = 0; j < 8; j++) {
            float2 e0 = *(const float2*)(ewRow + q0 + 8 * j + 2 * lc);
            float2 e1 = *(const float2*)(ewRow + 8 * (size_t)N_ + q0 + 8 * j + 2 * lc);
            float s0 = Sc[j][0] * e0.x, s1 = Sc[j][1] * e0.y;
            float s2 = Sc[j][2] * e1.x, s3 = Sc[j][3] * e1.y;
            __nv_bfloat16 h0, l0, h1, l1, h2, l2, h3, l3;
            split_bf(s0, h0, l0); split_bf(s1, h1, l1);
            split_bf(s2, h2, l2); split_bf(s3, h3, l3);
            int t = j >> 1, half = (j & 1) * 2;
            Ah[t][half + 0] = pack_bf2(h0, h1);
            Ah[t][half + 1] = pack_bf2(h2, h3);
            Al[t][half + 0] = pack_bf2(l0, l1);
            Al[t][half + 1] = pack_bf2(l2, l3);
        }

        // ---- Stage B: O[16x128] += S . hQ (B from hT, k = q), 3 passes ----
#pragma unroll
        for (int qb = 0; qb < 4; qb++) {
#pragma unroll
            for (int nb = 0; nb < 16; nb++) {
                const int bw = (nb * 8 + lr) * HTW + qb * 8 + lc;
                uint32_t bh0 = sHTH[bw], bh1 = sHTH[bw + 4];
                uint32_t bl0 = sHTL[bw], bl1 = sHTL[bw + 4];
                MMA16816(Oc[nb], Ah[qb][0], Ah[qb][1], Ah[qb][2], Ah[qb][3], bh0, bh1);
                MMA16816(Oc[nb], Ah[qb][0], Ah[qb][1], Ah[qb][2], Ah[qb][3], bl0, bl1);
                MMA16816(Oc[nb], Al[qb][0], Al[qb][1], Al[qb][2], Al[qb][3], bh0, bh1);
            }
        }
    }

    // ---- epilogue: fragment rows m0+lr and m0+lr+8 ----
    float* orow0 = out + ((size_t)b * N_ + p0 + m0 + lr) * H_;
    float* orow8 = orow0 + 8 * H_;
#pragma unroll
    for (int nb = 0; nb < 16; nb++) {
        float2 v0, v1;
        v0.x = Oc[nb][0]; v0.y = Oc[nb][1];
        v1.x = Oc[nb][2]; v1.y = Oc[nb][3];
        if (do_relu) {
            v0.x = fmaxf(v0.x, 0.f); v0.y = fmaxf(v0.y, 0.f);
            v1.x = fmaxf(v1.x, 0.f); v1.y = fmaxf(v1.y, 0.f);
        }
        *(float2*)&orow0[nb * 8 + 2 * lc] = v0;
        *(float2*)&orow8[nb * 8 + 2 * lc] = v1;
    }
}

// ===========================================================================
extern "C" void kernel_launch(void* const* d_in, const int* in_sizes, int n_in,
                              void* d_out, int out_size)
{
    (void)in_sizes; (void)n_in; (void)out_size;
    const float* x  = (const float*)d_in[0];
    const float* ew = (const float*)d_in[1];
    const float* Wl[3] = {(const float*)d_in[2], (const float*)d_in[4], (const float*)d_in[6]};
    const float* bl[3] = {(const float*)d_in[3], (const float*)d_in[5], (const float*)d_in[7]};
    float* out = (float*)d_out;

    void *pnh, *pnl, *pth, *ptl, *pb;
    cudaGetSymbolAddress(&pnh, g_nh_hi);
    cudaGetSymbolAddress(&pnl, g_nh_lo);
    cudaGetSymbolAddress(&pth, g_hT_hi);
    cudaGetSymbolAddress(&ptl, g_hT_lo);
    cudaGetSymbolAddress(&pb,  g_buf);
    __nv_bfloat16* nh_hi = (__nv_bfloat16*)pnh;
    __nv_bfloat16* nh_lo = (__nv_bfloat16*)pnl;
    __nv_bfloat16* hT_hi = (__nv_bfloat16*)pth;
    __nv_bfloat16* hT_lo = (__nv_bfloat16*)ptl;
    float* buf = (float*)pb;

    cudaFuncSetAttribute(agg_mma_kernel,
                         cudaFuncAttributeMaxDynamicSharedMemorySize, AGG_SMEM);

    const float* cur = x;
    for (int l = 0; l < 3; l++) {
        lin_norm_kernel<<<dim3(N_ / 32, B_), 256>>>(cur, Wl[l], bl[l],
                                                    nh_hi, nh_lo, hT_hi, hT_lo);
        float* o = (l == 2) ? out : buf;
        agg_mma_kernel<<<dim3(N_ / 64, B_), 128, AGG_SMEM>>>(
            nh_hi, nh_lo, hT_hi, hT_lo, ew, o, (l < 2) ? 1 : 0);
        cur = buf;
    }
}